// round 3
// baseline (speedup 1.0000x reference)
#include <cuda_runtime.h>

#define B_ROWS 8192
#define D_DIM  128
#define C_CLS  100
#define MARGIN 0.3f
#define ROWS_PER_WARP 4
#define NBLK   256    // 8 warps/block * 4 rows/warp * 256 blocks = 8192 rows

__device__ float        g_partials[NBLK];
__device__ unsigned int g_done;   // zero at load; reset by last block each run

__device__ __forceinline__ int load_idx(const void* p, int i, int is64) {
    if (is64) return (int)((const long long*)p)[i];
    return ((const int*)p)[i];
}

__global__ __launch_bounds__(256)
void triplet_fused_kernel(const float* __restrict__ x,
                          const void*  __restrict__ targets,
                          const void*  __restrict__ ixs,
                          const float* __restrict__ brdf,
                          float*       __restrict__ out) {
    const int warp = threadIdx.x >> 5;
    const int lane = threadIdx.x & 31;
    const int row_base = (blockIdx.x * 8 + warp) * ROWS_PER_WARP;

    // ---- inline index-width detection (per warp, no barrier) ----
    // int64 LE with values < 2^31: odd 32-bit words all zero.
    // int32: odd words are targets[1..63] in [0,100) -> P(all 32 zero) ~ 1e-64.
    unsigned int hw = ((const unsigned int*)targets)[2 * lane + 1];
    const int is64 = (__ballot_sync(0xFFFFFFFFu, hw != 0u) == 0u);

    // ---- front-batched index loads (uniform per warp, L1-broadcast) ----
    int i0[ROWS_PER_WARP], i1[ROWS_PER_WARP];
    #pragma unroll
    for (int r = 0; r < ROWS_PER_WARP; r++) {
        i0[r] = load_idx(ixs, 2 * (row_base + r),     is64);
        i1[r] = load_idx(ixs, 2 * (row_base + r) + 1, is64);
    }

    // ---- 12 independent 512B gathers in flight ----
    float4 a[ROWS_PER_WARP], p0[ROWS_PER_WARP], p1[ROWS_PER_WARP];
    #pragma unroll
    for (int r = 0; r < ROWS_PER_WARP; r++) {
        a[r]  = ((const float4*)(x + (size_t)(row_base + r) * D_DIM))[lane];
        p0[r] = ((const float4*)(x + (size_t)i0[r] * D_DIM))[lane];
        p1[r] = ((const float4*)(x + (size_t)i1[r] * D_DIM))[lane];
    }

    float s0[ROWS_PER_WARP], s1[ROWS_PER_WARP];
    #pragma unroll
    for (int r = 0; r < ROWS_PER_WARP; r++) {
        float dx;
        dx = a[r].x - p0[r].x; s0[r]  = dx * dx;
        dx = a[r].y - p0[r].y; s0[r] += dx * dx;
        dx = a[r].z - p0[r].z; s0[r] += dx * dx;
        dx = a[r].w - p0[r].w; s0[r] += dx * dx;
        dx = a[r].x - p1[r].x; s1[r]  = dx * dx;
        dx = a[r].y - p1[r].y; s1[r] += dx * dx;
        dx = a[r].z - p1[r].z; s1[r] += dx * dx;
        dx = a[r].w - p1[r].w; s1[r] += dx * dx;
    }

    #pragma unroll
    for (int off = 16; off > 0; off >>= 1) {
        #pragma unroll
        for (int r = 0; r < ROWS_PER_WARP; r++) {
            s0[r] += __shfl_xor_sync(0xFFFFFFFFu, s0[r], off);
            s1[r] += __shfl_xor_sync(0xFFFFFFFFu, s1[r], off);
        }
    }
    // every lane now holds all 8 sums

    // ---- parallel epilogue: lane r handles row r (r < 4) ----
    float hinge = 0.0f;
    if (lane < ROWS_PER_WARP) {
        const int r   = lane;
        const int row = row_base + r;
        int tb = load_idx(targets, row,   is64);
        int t0 = load_idx(targets, i0[r], is64);
        int t1 = load_idx(targets, i1[r], is64);
        float md1 = brdf[tb * C_CLS + t0];
        float md2 = brdf[tb * C_CLS + t1];
        float d0 = sqrtf(fmaxf(s0[r], 1e-12f));
        float d1 = sqrtf(fmaxf(s1[r], 1e-12f));
        float diff = (md1 < md2) ? (d0 - d1) : (d1 - d0);
        hinge = fmaxf(diff + MARGIN, 0.0f);
    }
    // fixed-order pairwise sum of lanes 0..3 into lane 0
    hinge += __shfl_xor_sync(0xFFFFFFFFu, hinge, 1);
    hinge += __shfl_xor_sync(0xFFFFFFFFu, hinge, 2);

    __shared__ float wsum[8];
    __shared__ int   s_last;
    if (lane == 0) wsum[warp] = hinge;
    __syncthreads();

    if (threadIdx.x == 0) {
        float t = 0.0f;
        #pragma unroll
        for (int w = 0; w < 8; w++) t += wsum[w];
        g_partials[blockIdx.x] = t;
        __threadfence();
        unsigned int prev = atomicAdd(&g_done, 1u);
        s_last = (prev == (unsigned int)(gridDim.x - 1));
    }
    __syncthreads();

    // ---- last block: deterministic final reduction over 256 partials ----
    if (s_last) {
        __shared__ float s[256];
        s[threadIdx.x] = g_partials[threadIdx.x];
        __syncthreads();
        #pragma unroll
        for (int off = 128; off > 0; off >>= 1) {
            if (threadIdx.x < off) s[threadIdx.x] += s[threadIdx.x + off];
            __syncthreads();
        }
        if (threadIdx.x == 0) {
            out[0] = s[0] * (1.0f / (float)B_ROWS);
            g_done = 0u;   // reset for next graph replay
        }
    }
}

extern "C" void kernel_launch(void* const* d_in, const int* in_sizes, int n_in,
                              void* d_out, int out_size) {
    const float* x       = (const float*)d_in[0];  // inputs   [8192,128] f32
    const void*  targets = d_in[1];                // targets  [8192]     i32/i64
    const void*  ixs     = d_in[2];                // ixs      [8192,2]   i32/i64
    const float* brdf    = (const float*)d_in[3];  // brdf     [100,100]  f32
    float*       out     = (float*)d_out;

    triplet_fused_kernel<<<NBLK, 256>>>(x, targets, ixs, brdf, out);
}

// round 8
// speedup vs baseline: 1.2148x; 1.2148x over previous
#include <cuda_runtime.h>

#define B_ROWS 8192
#define D_DIM  128
#define C_CLS  100
#define MARGIN 0.3f
#define NBLK   1024   // 8 warps/block, 1 row per warp

__device__ float        g_accum;  // zero at load; reset by last block each run
__device__ unsigned int g_done;   // zero at load; reset by last block each run

__global__ __launch_bounds__(256, 8)
void triplet_fused_kernel(const float* __restrict__ x,
                          const void*  __restrict__ targets,
                          const void*  __restrict__ ixs,
                          const float* __restrict__ brdf,
                          float*       __restrict__ out) {
    const int warp = threadIdx.x >> 5;
    const int lane = threadIdx.x & 31;
    const int row  = blockIdx.x * 8 + warp;   // grid exactly covers B_ROWS

    // ---------- trip 1: independent, bounds-safe-for-both-widths loads ----------
    // detection word: int64 LE => odd 32-bit words of targets are all zero
    unsigned int hw = ((const unsigned int*)targets)[2 * lane + 1];
    // int32 interpretation of ixs[row]: 8 bytes at offset row*8 (in-bounds for both widths)
    int2 w32 = ((const int2*)ixs)[row];
    // anchor row (index-independent)
    float4 a = ((const float4*)(x + (size_t)row * D_DIM))[lane];
    // tb under int32 interpretation (in-bounds for both widths)
    int tb = ((const int*)targets)[row];

    const int is64 = (__ballot_sync(0xFFFFFFFFu, hw != 0u) == 0u);

    int i0 = w32.x;
    int i1 = w32.y;
    if (is64) {   // warp-uniform; only taken when buffers really are int64
        i0 = (int)((const long long*)ixs)[2 * row];
        i1 = (int)((const long long*)ixs)[2 * row + 1];
        tb = (int)((const long long*)targets)[row];
    }

    // ---------- trip 2: gathers dependent on i0/i1 ----------
    float4 p0 = ((const float4*)(x + (size_t)i0 * D_DIM))[lane];
    float4 p1 = ((const float4*)(x + (size_t)i1 * D_DIM))[lane];
    int t0 = is64 ? (int)((const long long*)targets)[i0] : ((const int*)targets)[i0];
    int t1 = is64 ? (int)((const long long*)targets)[i1] : ((const int*)targets)[i1];

    // ---------- trip 3 (overlaps the shuffle reduction) ----------
    float md1 = brdf[tb * C_CLS + t0];
    float md2 = brdf[tb * C_CLS + t1];

    float dx, s0, s1;
    dx = a.x - p0.x; s0  = dx * dx;
    dx = a.y - p0.y; s0 += dx * dx;
    dx = a.z - p0.z; s0 += dx * dx;
    dx = a.w - p0.w; s0 += dx * dx;
    dx = a.x - p1.x; s1  = dx * dx;
    dx = a.y - p1.y; s1 += dx * dx;
    dx = a.z - p1.z; s1 += dx * dx;
    dx = a.w - p1.w; s1 += dx * dx;

    #pragma unroll
    for (int off = 16; off > 0; off >>= 1) {
        s0 += __shfl_xor_sync(0xFFFFFFFFu, s0, off);
        s1 += __shfl_xor_sync(0xFFFFFFFFu, s1, off);
    }

    float d0 = sqrtf(fmaxf(s0, 1e-12f));
    float d1 = sqrtf(fmaxf(s1, 1e-12f));
    float diff = (md1 < md2) ? (d0 - d1) : (d1 - d0);
    float hinge = fmaxf(diff + MARGIN, 0.0f);

    __shared__ float wsum[8];
    __shared__ int   s_last;
    if (lane == 0) wsum[warp] = hinge;
    __syncthreads();

    if (threadIdx.x == 0) {
        float t = 0.0f;
        #pragma unroll
        for (int w = 0; w < 8; w++) t += wsum[w];
        atomicAdd(&g_accum, t);
        __threadfence();
        unsigned int prev = atomicAdd(&g_done, 1u);
        s_last = (prev == (unsigned int)(gridDim.x - 1));
    }
    __syncthreads();

    if (s_last && threadIdx.x == 0) {
        // all 1024 atomicAdds are visible (g_done reached 1024 after fences)
        float total = g_accum;
        out[0] = total * (1.0f / (float)B_ROWS);
        g_accum = 0.0f;   // reset for next graph replay
        __threadfence();
        g_done = 0u;
    }
}

extern "C" void kernel_launch(void* const* d_in, const int* in_sizes, int n_in,
                              void* d_out, int out_size) {
    const float* x       = (const float*)d_in[0];  // inputs   [8192,128] f32
    const void*  targets = d_in[1];                // targets  [8192]     i32/i64
    const void*  ixs     = d_in[2];                // ixs      [8192,2]   i32/i64
    const float* brdf    = (const float*)d_in[3];  // brdf     [100,100]  f32
    float*       out     = (float*)d_out;

    triplet_fused_kernel<<<NBLK, 256>>>(x, targets, ixs, brdf, out);
}